// round 9
// baseline (speedup 1.0000x reference)
#include <cuda_runtime.h>
#include <cuda_fp16.h>
#include <cuda_bf16.h>
#include <cstdint>

// GCN, folded normalization, fp16 tables, fp32 accumulation.
//   xw'[v] = (x@W)[v] * dinvs[v]   (fp16)
//   out[d] = dinvs[d] * ( sum_edges xw'[s] + xw'[d] ) + b
// Schedule (6 launches; launch 3 = agg<0> so ncu profiles it):
//   0: count_rank (atomics; packs (rank<<17)|dst)
//   1: scan (single kernel, soft global barrier across 98 resident blocks;
//            re-zeros g_cnt; g_arrive reset by final_kernel)
//   2: fatB: place (atomic-free scatter) || gemm1 (prescaled fp16 xw)
//   3: agg<0>   4: agg<1>   5: final

#define N_MAX 100000
#define E_MAX 3200000
#define IN_CH 128
#define HID   32
#define LN_EPS 1e-5f
#define SCAN_B 1024
#define ZROW  N_MAX

// ---------------- device scratch (zero-initialized at load) ----------------
__device__ int    g_cnt[N_MAX];            // stays zero between calls
__device__ int    g_rowstart[N_MAX + 1];
__device__ float  g_dinvs[N_MAX];
__device__ int    g_rd[E_MAX + 4];         // (rank<<17) | dst
__device__ int    g_src[E_MAX + 32];
__device__ int    g_bsum[128];
__device__ int    g_arrive;                // soft-barrier counter (reset by final)
__device__ __align__(128) __half g_xw[(N_MAX + 1) * HID];   // ZROW row stays 0
__device__ __align__(128) __half g_hw2[(N_MAX + 1) * HID];  // ZROW row stays 0
__device__ float  g_hw3[(N_MAX + 1) * 2];                   // ZROW row stays 0

// ---------------- 0: count + rank (packed) ----------------
__global__ void count_rank_kernel(const int* __restrict__ ei, int e) {
    int i = blockIdx.x * blockDim.x + threadIdx.x;
    int n4 = e >> 2;
    if (i < n4) {
        int4 d4 = ((const int4*)(ei + e))[i];
        int4 p4;
        p4.x = (atomicAdd(&g_cnt[d4.x], 1) << 17) | d4.x;
        p4.y = (atomicAdd(&g_cnt[d4.y], 1) << 17) | d4.y;
        p4.z = (atomicAdd(&g_cnt[d4.z], 1) << 17) | d4.z;
        p4.w = (atomicAdd(&g_cnt[d4.w], 1) << 17) | d4.w;
        ((int4*)g_rd)[i] = p4;
    }
    if (i == 0) {
        for (int j = n4 << 2; j < e; j++) {
            int d = ei[e + j];
            g_rd[j] = (atomicAdd(&g_cnt[d], 1) << 17) | d;
        }
    }
}

// ---------------- 1: single-kernel scan (soft global barrier) -------------
// grid = nb (<=128 <= 148 SMs) so all blocks are co-resident; spinning is safe.
__global__ void scan_kernel(int n, int nb) {
    __shared__ int wsum[32];
    __shared__ int boff_s;
    int tid = threadIdx.x, lane = tid & 31, wid = tid >> 5;

    int i = blockIdx.x * SCAN_B + tid;
    int v = (i < n) ? g_cnt[i] : 0;
    int x = v;
    #pragma unroll
    for (int d = 1; d < 32; d <<= 1) {
        int t = __shfl_up_sync(0xFFFFFFFFu, x, d);
        if (lane >= d) x += t;
    }
    if (lane == 31) wsum[wid] = x;
    __syncthreads();
    if (wid == 0) {
        int s = wsum[lane];
        #pragma unroll
        for (int d = 1; d < 32; d <<= 1) {
            int t = __shfl_up_sync(0xFFFFFFFFu, s, d);
            if (lane >= d) s += t;
        }
        wsum[lane] = s;
    }
    if (tid == 0) boff_s = 0;
    __syncthreads();

    // publish this block's total, soft-barrier until all published
    if (tid == 0) {
        g_bsum[blockIdx.x] = wsum[31];
        __threadfence();
        atomicAdd(&g_arrive, 1);
        while (*((volatile int*)&g_arrive) < nb) { }
        __threadfence();
    }
    __syncthreads();

    // block offset = sum of g_bsum[0..bid)
    if (tid < 128) {
        int bv = (tid < blockIdx.x) ? g_bsum[tid] : 0;
        #pragma unroll
        for (int d = 16; d; d >>= 1) bv += __shfl_xor_sync(0xFFFFFFFFu, bv, d);
        if (lane == 0 && bv) atomicAdd(&boff_s, bv);
    }
    __syncthreads();

    if (i < n) {
        int excl = boff_s + (wid > 0 ? wsum[wid - 1] : 0) + x - v;
        g_rowstart[i] = excl;
        g_dinvs[i] = rsqrtf((float)v + 1.0f);
        g_cnt[i] = 0;                       // self-clean for next call
        if (i == n - 1) g_rowstart[n] = excl + v;
    }
}

// ---------------- 2 fatB: place branch || gemm1 (prescaled) branch --------
__global__ void place_gemm_kernel(const int* __restrict__ ei,
                                  const float* __restrict__ x,
                                  const float* __restrict__ W1,
                                  int n, int e, int gemmBlocks) {
    __shared__ __align__(16) float Ws[128 * 32];
    __shared__ __align__(16) float xs[128 * 33];
    int tid = threadIdx.x;

    if (blockIdx.x < gemmBlocks) {
        // ---- gemm1: g_xw = fp16((x @ W1) * dinvs) ----
        for (int i = tid; i < 128 * 32; i += 256) Ws[i] = W1[i];
        int tx = tid & 7;
        int ty = tid >> 3;
        int wid = tid >> 5, lane = tid & 31;
        int nodeBase = blockIdx.x * 128;

        unsigned long long acc2[4][2];
        #pragma unroll
        for (int i = 0; i < 4; i++) { acc2[i][0] = 0ull; acc2[i][1] = 0ull; }

        for (int kc = 0; kc < 4; kc++) {
            __syncthreads();
            for (int r = wid; r < 128; r += 8) {
                int gn = nodeBase + r;
                float v = 0.f;
                if (gn < n) v = x[gn * IN_CH + kc * 32 + lane];
                xs[r * 33 + lane] = v;
            }
            __syncthreads();
            #pragma unroll
            for (int k = 0; k < 32; k++) {
                const unsigned long long* wp =
                    (const unsigned long long*)&Ws[(kc * 32 + k) * 32 + tx * 4];
                unsigned long long w0 = wp[0], w1 = wp[1];
                #pragma unroll
                for (int i = 0; i < 4; i++) {
                    float xv = xs[(ty * 4 + i) * 33 + k];
                    unsigned long long xp;
                    asm("mov.b64 %0, {%1, %1};" : "=l"(xp) : "f"(xv));
                    asm("fma.rn.f32x2 %0, %1, %2, %0;" : "+l"(acc2[i][0]) : "l"(xp), "l"(w0));
                    asm("fma.rn.f32x2 %0, %1, %2, %0;" : "+l"(acc2[i][1]) : "l"(xp), "l"(w1));
                }
            }
        }
        #pragma unroll
        for (int i = 0; i < 4; i++) {
            int gn = nodeBase + ty * 4 + i;
            if (gn < n) {
                float ds = g_dinvs[gn];
                float r0, r1, r2, r3;
                asm("mov.b64 {%0, %1}, %2;" : "=f"(r0), "=f"(r1) : "l"(acc2[i][0]));
                asm("mov.b64 {%0, %1}, %2;" : "=f"(r2), "=f"(r3) : "l"(acc2[i][1]));
                __half2 h01 = __floats2half2_rn(r0 * ds, r1 * ds);
                __half2 h23 = __floats2half2_rn(r2 * ds, r3 * ds);
                uint2 st;
                st.x = *(unsigned*)&h01;
                st.y = *(unsigned*)&h23;
                *(uint2*)&g_xw[gn * HID + tx * 4] = st;
            }
        }
    } else {
        // ---- place: pos = rowstart[dst] + rank (no atomics) ----
        int i = (blockIdx.x - gemmBlocks) * blockDim.x + tid;
        int n4 = e >> 2;
        if (i < n4) {
            int4 s4 = ((const int4*)ei)[i];
            int4 p4 = ((const int4*)g_rd)[i];
            g_src[g_rowstart[p4.x & 0x1FFFF] + (p4.x >> 17)] = s4.x;
            g_src[g_rowstart[p4.y & 0x1FFFF] + (p4.y >> 17)] = s4.y;
            g_src[g_rowstart[p4.z & 0x1FFFF] + (p4.z >> 17)] = s4.z;
            g_src[g_rowstart[p4.w & 0x1FFFF] + (p4.w >> 17)] = s4.w;
        }
        if (i == 0) {
            for (int j = n4 << 2; j < e; j++)
                g_src[g_rowstart[g_rd[j] & 0x1FFFF] + (g_rd[j] >> 17)] = ei[j];
        }
    }
}

// ---------------- 3/4: fp16 gather-agg + bias + LN + ReLU + next GEMM -----
template <int MODE>
__global__ void agg_kernel(const float* __restrict__ b,
                           const float* __restrict__ g,
                           const float* __restrict__ be,
                           const float* __restrict__ Wn, int n) {
    const __half* __restrict__ xw = (MODE == 0) ? g_xw : g_hw2;
    __shared__ float Wns[32 * 32];
    __shared__ float tr[8 * 32];
    int tid = threadIdx.x, lane = tid & 31, wid = tid >> 5;
    int nload = (MODE == 0) ? 1024 : 64;
    for (int i = tid; i < nload; i += blockDim.x) Wns[i] = Wn[i];
    __syncthreads();

    int node = blockIdx.x * 8 + wid;
    if (node >= n) return;

    int rs = g_rowstart[node];
    int re = g_rowstart[node + 1];
    int cg = lane & 7;
    int eg = lane >> 3;

    float f0 = 0.f, f1 = 0.f, f2 = 0.f, f3 = 0.f;
    int idx0 = rs + lane;
    int sidx = (idx0 < re) ? __ldg(&g_src[idx0]) : ZROW;
    for (int base = rs; base < re; base += 32) {
        // prefetch next batch's indices before consuming this one
        int nbase = base + 32;
        int nidx = nbase + lane;
        int nsidx = (nbase < re && nidx < re) ? __ldg(&g_src[nidx]) : ZROW;
        #pragma unroll
        for (int it = 0; it < 8; it++) {
            int s = __shfl_sync(0xFFFFFFFFu, sidx, it * 4 + eg);
            uint2 v = __ldg((const uint2*)&xw[s * HID + cg * 4]);
            float2 lo = __half22float2(*(__half2*)&v.x);
            float2 hi = __half22float2(*(__half2*)&v.y);
            f0 += lo.x; f1 += lo.y; f2 += hi.x; f3 += hi.y;
        }
        sidx = nsidx;
    }

    #pragma unroll
    for (int m = 8; m <= 16; m <<= 1) {
        f0 += __shfl_xor_sync(0xFFFFFFFFu, f0, m);
        f1 += __shfl_xor_sync(0xFFFFFFFFu, f1, m);
        f2 += __shfl_xor_sync(0xFFFFFFFFu, f2, m);
        f3 += __shfl_xor_sync(0xFFFFFFFFu, f3, m);
    }
    if (eg == 0) {
        float4 st; st.x = f0; st.y = f1; st.z = f2; st.w = f3;
        *(float4*)&tr[wid * 32 + cg * 4] = st;
    }
    __syncwarp();
    float acc = tr[wid * 32 + lane];

    float ds = g_dinvs[node];
    acc = (acc + __half2float(xw[node * HID + lane])) * ds + b[lane];

    float s = acc;
    #pragma unroll
    for (int d = 16; d; d >>= 1) s += __shfl_xor_sync(0xFFFFFFFFu, s, d);
    float mu = s * (1.0f / 32.0f);
    float diff = acc - mu;
    float v2 = diff * diff;
    #pragma unroll
    for (int d = 16; d; d >>= 1) v2 += __shfl_xor_sync(0xFFFFFFFFu, v2, d);
    float var = v2 * (1.0f / 32.0f);
    float y = diff * rsqrtf(var + LN_EPS) * g[lane] + be[lane];
    float h = fmaxf(y, 0.f);

    if (MODE == 0) {
        float o0 = 0.f, o1 = 0.f;
        #pragma unroll
        for (int k = 0; k < 32; k += 2) {
            float h0 = __shfl_sync(0xFFFFFFFFu, h, k);
            float h1 = __shfl_sync(0xFFFFFFFFu, h, k + 1);
            o0 = fmaf(h0, Wns[k * 32 + lane], o0);
            o1 = fmaf(h1, Wns[(k + 1) * 32 + lane], o1);
        }
        g_hw2[node * HID + lane] = __float2half((o0 + o1) * ds);
    } else {
        float p0 = h * Wns[lane * 2 + 0];
        float p1 = h * Wns[lane * 2 + 1];
        #pragma unroll
        for (int d = 16; d; d >>= 1) {
            p0 += __shfl_xor_sync(0xFFFFFFFFu, p0, d);
            p1 += __shfl_xor_sync(0xFFFFFFFFu, p1, d);
        }
        if (lane == 0) {
            float2 r; r.x = p0 * ds; r.y = p1 * ds;
            *(float2*)&g_hw3[node * 2] = r;
        }
    }
}

// ---------------- 5: final conv (OUT=2), also resets g_arrive -------------
__global__ void final_kernel(const float* __restrict__ b3,
                             float* __restrict__ out, int n) {
    if (blockIdx.x == 0 && threadIdx.x == 0) g_arrive = 0;  // for next call
    int tid = threadIdx.x, lane = tid & 31, wid = tid >> 5;
    int node = blockIdx.x * 8 + wid;
    if (node >= n) return;
    int rs = g_rowstart[node];
    int re = g_rowstart[node + 1];
    float a0 = 0.f, a1 = 0.f;
    for (int idx = rs + lane; idx < re; idx += 32) {
        float2 v = *(const float2*)&g_hw3[g_src[idx] * 2];
        a0 += v.x;
        a1 += v.y;
    }
    #pragma unroll
    for (int d = 16; d; d >>= 1) {
        a0 += __shfl_xor_sync(0xFFFFFFFFu, a0, d);
        a1 += __shfl_xor_sync(0xFFFFFFFFu, a1, d);
    }
    if (lane == 0) {
        float2 self = *(const float2*)&g_hw3[node * 2];
        float ds = g_dinvs[node];
        out[node * 2 + 0] = (a0 + self.x) * ds + b3[0];
        out[node * 2 + 1] = (a1 + self.y) * ds + b3[1];
    }
}

// ---------------- launch ----------------
extern "C" void kernel_launch(void* const* d_in, const int* in_sizes, int n_in,
                              void* d_out, int out_size) {
    const float* x   = (const float*)d_in[0];
    const int*   ei  = (const int*)d_in[1];
    const float* W1  = (const float*)d_in[2];
    const float* b1  = (const float*)d_in[3];
    const float* g1  = (const float*)d_in[4];
    const float* be1 = (const float*)d_in[5];
    const float* W2  = (const float*)d_in[6];
    const float* b2  = (const float*)d_in[7];
    const float* g2  = (const float*)d_in[8];
    const float* be2 = (const float*)d_in[9];
    const float* W3  = (const float*)d_in[10];
    const float* b3  = (const float*)d_in[11];
    float* out = (float*)d_out;

    int n = in_sizes[0] / IN_CH;   // 100000
    int e = in_sizes[1] / 2;       // 3200000
    int nb = (n + SCAN_B - 1) / SCAN_B;          // 98 <= 148 SMs
    int gemmBlocks  = (n + 127) / 128;
    int placeBlocks = ((e >> 2) + 255) / 256;

    count_rank_kernel<<<((e >> 2) + 255) / 256, 256>>>(ei, e);
    scan_kernel<<<nb, SCAN_B>>>(n, nb);
    place_gemm_kernel<<<gemmBlocks + placeBlocks, 256>>>(ei, x, W1, n, e, gemmBlocks);
    agg_kernel<0><<<(n + 7) / 8, 256>>>(b1, g1, be1, W2, n);    // launch idx 3 -> profiled
    agg_kernel<1><<<(n + 7) / 8, 256>>>(b2, g2, be2, W3, n);
    final_kernel<<<(n + 7) / 8, 256>>>(b3, out, n);
}

// round 11
// speedup vs baseline: 1.0118x; 1.0118x over previous
#include <cuda_runtime.h>
#include <cuda_fp16.h>
#include <cuda_bf16.h>
#include <cstdint>

// GCN, folded normalization, fp16 tables, fp32 accumulation.
//   xw'[v] = (x@W)[v] * dinvs[v]   (fp16)
//   out[d] = dinvs[d] * ( sum_edges xw'[s] + xw'[d] ) + b
// Aggregation layout (L1/issue-optimized): lane -> (eg = lane>>2 edge slot,
// cg = lane&3 channel group of 8). Per 32-edge batch: 4 shfl + 4 LDG.128.
// Schedule: count_rank -> fused scan (soft barrier) -> place||gemm1 ->
// agg<0> -> agg<1> -> final.

#define N_MAX 100000
#define E_MAX 3200000
#define IN_CH 128
#define HID   32
#define LN_EPS 1e-5f
#define SCAN_B 1024
#define ZROW  N_MAX

// ---------------- device scratch (zero-initialized at load) ----------------
__device__ int    g_cnt[N_MAX];            // stays zero between calls
__device__ int    g_rowstart[N_MAX + 1];
__device__ float  g_dinvs[N_MAX];
__device__ int    g_rd[E_MAX + 4];         // (rank<<17) | dst
__device__ int    g_src[E_MAX + 32];
__device__ int    g_bsum[128];
__device__ int    g_arrive;                // soft-barrier counter (reset by final)
__device__ __align__(128) __half g_xw[(N_MAX + 1) * HID];   // ZROW row stays 0
__device__ __align__(128) __half g_hw2[(N_MAX + 1) * HID];  // ZROW row stays 0
__device__ float  g_hw3[(N_MAX + 1) * 2];                   // ZROW row stays 0

// ---------------- 0: count + rank (packed) ----------------
__global__ void count_rank_kernel(const int* __restrict__ ei, int e) {
    int i = blockIdx.x * blockDim.x + threadIdx.x;
    int n4 = e >> 2;
    if (i < n4) {
        int4 d4 = ((const int4*)(ei + e))[i];
        int4 p4;
        p4.x = (atomicAdd(&g_cnt[d4.x], 1) << 17) | d4.x;
        p4.y = (atomicAdd(&g_cnt[d4.y], 1) << 17) | d4.y;
        p4.z = (atomicAdd(&g_cnt[d4.z], 1) << 17) | d4.z;
        p4.w = (atomicAdd(&g_cnt[d4.w], 1) << 17) | d4.w;
        ((int4*)g_rd)[i] = p4;
    }
    if (i == 0) {
        for (int j = n4 << 2; j < e; j++) {
            int d = ei[e + j];
            g_rd[j] = (atomicAdd(&g_cnt[d], 1) << 17) | d;
        }
    }
}

// ---------------- 1: single-kernel scan (soft global barrier) -------------
__global__ void scan_kernel(int n, int nb) {
    __shared__ int wsum[32];
    __shared__ int boff_s;
    int tid = threadIdx.x, lane = tid & 31, wid = tid >> 5;

    int i = blockIdx.x * SCAN_B + tid;
    int v = (i < n) ? g_cnt[i] : 0;
    int x = v;
    #pragma unroll
    for (int d = 1; d < 32; d <<= 1) {
        int t = __shfl_up_sync(0xFFFFFFFFu, x, d);
        if (lane >= d) x += t;
    }
    if (lane == 31) wsum[wid] = x;
    __syncthreads();
    if (wid == 0) {
        int s = wsum[lane];
        #pragma unroll
        for (int d = 1; d < 32; d <<= 1) {
            int t = __shfl_up_sync(0xFFFFFFFFu, s, d);
            if (lane >= d) s += t;
        }
        wsum[lane] = s;
    }
    if (tid == 0) boff_s = 0;
    __syncthreads();

    if (tid == 0) {
        g_bsum[blockIdx.x] = wsum[31];
        __threadfence();
        atomicAdd(&g_arrive, 1);
        while (*((volatile int*)&g_arrive) < nb) { }
        __threadfence();
    }
    __syncthreads();

    if (tid < 128) {
        int bv = (tid < blockIdx.x) ? g_bsum[tid] : 0;
        #pragma unroll
        for (int d = 16; d; d >>= 1) bv += __shfl_xor_sync(0xFFFFFFFFu, bv, d);
        if (lane == 0 && bv) atomicAdd(&boff_s, bv);
    }
    __syncthreads();

    if (i < n) {
        int excl = boff_s + (wid > 0 ? wsum[wid - 1] : 0) + x - v;
        g_rowstart[i] = excl;
        g_dinvs[i] = rsqrtf((float)v + 1.0f);
        g_cnt[i] = 0;                       // self-clean for next call
        if (i == n - 1) g_rowstart[n] = excl + v;
    }
}

// ---------------- 2 fat: place branch || gemm1 (prescaled) branch ---------
__global__ void place_gemm_kernel(const int* __restrict__ ei,
                                  const float* __restrict__ x,
                                  const float* __restrict__ W1,
                                  int n, int e, int gemmBlocks) {
    __shared__ __align__(16) float Ws[128 * 32];
    __shared__ __align__(16) float xs[128 * 33];
    int tid = threadIdx.x;

    if (blockIdx.x < gemmBlocks) {
        for (int i = tid; i < 128 * 32; i += 256) Ws[i] = W1[i];
        int tx = tid & 7;
        int ty = tid >> 3;
        int wid = tid >> 5, lane = tid & 31;
        int nodeBase = blockIdx.x * 128;

        unsigned long long acc2[4][2];
        #pragma unroll
        for (int i = 0; i < 4; i++) { acc2[i][0] = 0ull; acc2[i][1] = 0ull; }

        for (int kc = 0; kc < 4; kc++) {
            __syncthreads();
            for (int r = wid; r < 128; r += 8) {
                int gn = nodeBase + r;
                float v = 0.f;
                if (gn < n) v = x[gn * IN_CH + kc * 32 + lane];
                xs[r * 33 + lane] = v;
            }
            __syncthreads();
            #pragma unroll
            for (int k = 0; k < 32; k++) {
                const unsigned long long* wp =
                    (const unsigned long long*)&Ws[(kc * 32 + k) * 32 + tx * 4];
                unsigned long long w0 = wp[0], w1 = wp[1];
                #pragma unroll
                for (int i = 0; i < 4; i++) {
                    float xv = xs[(ty * 4 + i) * 33 + k];
                    unsigned long long xp;
                    asm("mov.b64 %0, {%1, %1};" : "=l"(xp) : "f"(xv));
                    asm("fma.rn.f32x2 %0, %1, %2, %0;" : "+l"(acc2[i][0]) : "l"(xp), "l"(w0));
                    asm("fma.rn.f32x2 %0, %1, %2, %0;" : "+l"(acc2[i][1]) : "l"(xp), "l"(w1));
                }
            }
        }
        #pragma unroll
        for (int i = 0; i < 4; i++) {
            int gn = nodeBase + ty * 4 + i;
            if (gn < n) {
                float ds = g_dinvs[gn];
                float r0, r1, r2, r3;
                asm("mov.b64 {%0, %1}, %2;" : "=f"(r0), "=f"(r1) : "l"(acc2[i][0]));
                asm("mov.b64 {%0, %1}, %2;" : "=f"(r2), "=f"(r3) : "l"(acc2[i][1]));
                __half2 h01 = __floats2half2_rn(r0 * ds, r1 * ds);
                __half2 h23 = __floats2half2_rn(r2 * ds, r3 * ds);
                uint2 st;
                st.x = *(unsigned*)&h01;
                st.y = *(unsigned*)&h23;
                *(uint2*)&g_xw[gn * HID + tx * 4] = st;
            }
        }
    } else {
        int i = (blockIdx.x - gemmBlocks) * blockDim.x + tid;
        int n4 = e >> 2;
        if (i < n4) {
            int4 s4 = ((const int4*)ei)[i];
            int4 p4 = ((const int4*)g_rd)[i];
            g_src[g_rowstart[p4.x & 0x1FFFF] + (p4.x >> 17)] = s4.x;
            g_src[g_rowstart[p4.y & 0x1FFFF] + (p4.y >> 17)] = s4.y;
            g_src[g_rowstart[p4.z & 0x1FFFF] + (p4.z >> 17)] = s4.z;
            g_src[g_rowstart[p4.w & 0x1FFFF] + (p4.w >> 17)] = s4.w;
        }
        if (i == 0) {
            for (int j = n4 << 2; j < e; j++)
                g_src[g_rowstart[g_rd[j] & 0x1FFFF] + (g_rd[j] >> 17)] = ei[j];
        }
    }
}

// ---------------- 3/4: uint4 gather-agg + bias + LN + ReLU + next GEMM ----
// lane -> (eg = lane>>2 in 0..7 edge slots, cg = lane&3 channel group of 8)
template <int MODE>
__global__ void agg_kernel(const float* __restrict__ b,
                           const float* __restrict__ g,
                           const float* __restrict__ be,
                           const float* __restrict__ Wn, int n) {
    const __half* __restrict__ xw = (MODE == 0) ? g_xw : g_hw2;
    __shared__ float Wns[32 * 32];
    __shared__ float tr[8 * 32];
    int tid = threadIdx.x, lane = tid & 31, wid = tid >> 5;
    int nload = (MODE == 0) ? 1024 : 64;
    for (int i = tid; i < nload; i += blockDim.x) Wns[i] = Wn[i];
    __syncthreads();

    int node = blockIdx.x * 8 + wid;
    if (node >= n) return;

    int rs = g_rowstart[node];
    int re = g_rowstart[node + 1];
    int cg = lane & 3;    // channels cg*8 .. cg*8+7
    int eg = lane >> 2;   // edge slot 0..7

    float f0 = 0.f, f1 = 0.f, f2 = 0.f, f3 = 0.f;
    float f4 = 0.f, f5 = 0.f, f6 = 0.f, f7 = 0.f;
    for (int base = rs; base < re; base += 32) {
        int idx = base + lane;
        int sidx = (idx < re) ? g_src[idx] : ZROW;
        #pragma unroll
        for (int it = 0; it < 4; it++) {
            int s = __shfl_sync(0xFFFFFFFFu, sidx, it * 8 + eg);
            uint4 v = *(const uint4*)&xw[s * HID + cg * 8];   // 8 halves
            float2 pa = __half22float2(*(__half2*)&v.x);
            float2 pb = __half22float2(*(__half2*)&v.y);
            float2 pc = __half22float2(*(__half2*)&v.z);
            float2 pd = __half22float2(*(__half2*)&v.w);
            f0 += pa.x; f1 += pa.y; f2 += pb.x; f3 += pb.y;
            f4 += pc.x; f5 += pc.y; f6 += pd.x; f7 += pd.y;
        }
    }

    // reduce across 8 edge slots (lane bits 2,3,4)
    #pragma unroll
    for (int m = 4; m <= 16; m <<= 1) {
        f0 += __shfl_xor_sync(0xFFFFFFFFu, f0, m);
        f1 += __shfl_xor_sync(0xFFFFFFFFu, f1, m);
        f2 += __shfl_xor_sync(0xFFFFFFFFu, f2, m);
        f3 += __shfl_xor_sync(0xFFFFFFFFu, f3, m);
        f4 += __shfl_xor_sync(0xFFFFFFFFu, f4, m);
        f5 += __shfl_xor_sync(0xFFFFFFFFu, f5, m);
        f6 += __shfl_xor_sync(0xFFFFFFFFu, f6, m);
        f7 += __shfl_xor_sync(0xFFFFFFFFu, f7, m);
    }
    if (eg == 0) {
        float4 s0; s0.x = f0; s0.y = f1; s0.z = f2; s0.w = f3;
        float4 s1; s1.x = f4; s1.y = f5; s1.z = f6; s1.w = f7;
        *(float4*)&tr[wid * 32 + cg * 8]     = s0;
        *(float4*)&tr[wid * 32 + cg * 8 + 4] = s1;
    }
    __syncwarp();
    float acc = tr[wid * 32 + lane];

    float ds = g_dinvs[node];
    acc = (acc + __half2float(xw[node * HID + lane])) * ds + b[lane];

    // LayerNorm over the 32 lanes
    float s = acc;
    #pragma unroll
    for (int d = 16; d; d >>= 1) s += __shfl_xor_sync(0xFFFFFFFFu, s, d);
    float mu = s * (1.0f / 32.0f);
    float diff = acc - mu;
    float v2 = diff * diff;
    #pragma unroll
    for (int d = 16; d; d >>= 1) v2 += __shfl_xor_sync(0xFFFFFFFFu, v2, d);
    float var = v2 * (1.0f / 32.0f);
    float y = diff * rsqrtf(var + LN_EPS) * g[lane] + be[lane];
    float h = fmaxf(y, 0.f);

    if (MODE == 0) {
        float o0 = 0.f, o1 = 0.f;
        #pragma unroll
        for (int k = 0; k < 32; k += 2) {
            float h0 = __shfl_sync(0xFFFFFFFFu, h, k);
            float h1 = __shfl_sync(0xFFFFFFFFu, h, k + 1);
            o0 = fmaf(h0, Wns[k * 32 + lane], o0);
            o1 = fmaf(h1, Wns[(k + 1) * 32 + lane], o1);
        }
        g_hw2[node * HID + lane] = __float2half((o0 + o1) * ds);
    } else {
        float p0 = h * Wns[lane * 2 + 0];
        float p1 = h * Wns[lane * 2 + 1];
        #pragma unroll
        for (int d = 16; d; d >>= 1) {
            p0 += __shfl_xor_sync(0xFFFFFFFFu, p0, d);
            p1 += __shfl_xor_sync(0xFFFFFFFFu, p1, d);
        }
        if (lane == 0) {
            float2 r; r.x = p0 * ds; r.y = p1 * ds;
            *(float2*)&g_hw3[node * 2] = r;
        }
    }
}

// ---------------- 5: final conv (OUT=2), also resets g_arrive -------------
__global__ void final_kernel(const float* __restrict__ b3,
                             float* __restrict__ out, int n) {
    if (blockIdx.x == 0 && threadIdx.x == 0) g_arrive = 0;  // for next call
    int tid = threadIdx.x, lane = tid & 31, wid = tid >> 5;
    int node = blockIdx.x * 8 + wid;
    if (node >= n) return;
    int rs = g_rowstart[node];
    int re = g_rowstart[node + 1];
    float a0 = 0.f, a1 = 0.f;
    for (int idx = rs + lane; idx < re; idx += 32) {
        float2 v = *(const float2*)&g_hw3[g_src[idx] * 2];
        a0 += v.x;
        a1 += v.y;
    }
    #pragma unroll
    for (int d = 16; d; d >>= 1) {
        a0 += __shfl_xor_sync(0xFFFFFFFFu, a0, d);
        a1 += __shfl_xor_sync(0xFFFFFFFFu, a1, d);
    }
    if (lane == 0) {
        float2 self = *(const float2*)&g_hw3[node * 2];
        float ds = g_dinvs[node];
        out[node * 2 + 0] = (a0 + self.x) * ds + b3[0];
        out[node * 2 + 1] = (a1 + self.y) * ds + b3[1];
    }
}

// ---------------- launch ----------------
extern "C" void kernel_launch(void* const* d_in, const int* in_sizes, int n_in,
                              void* d_out, int out_size) {
    const float* x   = (const float*)d_in[0];
    const int*   ei  = (const int*)d_in[1];
    const float* W1  = (const float*)d_in[2];
    const float* b1  = (const float*)d_in[3];
    const float* g1  = (const float*)d_in[4];
    const float* be1 = (const float*)d_in[5];
    const float* W2  = (const float*)d_in[6];
    const float* b2  = (const float*)d_in[7];
    const float* g2  = (const float*)d_in[8];
    const float* be2 = (const float*)d_in[9];
    const float* W3  = (const float*)d_in[10];
    const float* b3  = (const float*)d_in[11];
    float* out = (float*)d_out;

    int n = in_sizes[0] / IN_CH;   // 100000
    int e = in_sizes[1] / 2;       // 3200000
    int nb = (n + SCAN_B - 1) / SCAN_B;          // 98 <= 148 SMs
    int gemmBlocks  = (n + 127) / 128;
    int placeBlocks = ((e >> 2) + 255) / 256;

    count_rank_kernel<<<((e >> 2) + 255) / 256, 256>>>(ei, e);
    scan_kernel<<<nb, SCAN_B>>>(n, nb);
    place_gemm_kernel<<<gemmBlocks + placeBlocks, 256>>>(ei, x, W1, n, e, gemmBlocks);
    agg_kernel<0><<<(n + 7) / 8, 256>>>(b1, g1, be1, W2, n);    // launch idx 3 -> profiled
    agg_kernel<1><<<(n + 7) / 8, 256>>>(b2, g2, be2, W3, n);
    final_kernel<<<(n + 7) / 8, 256>>>(b3, out, n);
}